// round 16
// baseline (speedup 1.0000x reference)
#include <cuda_runtime.h>
#include <cuda_bf16.h>

#define RIR_LEN   8000
#define NIMG      1561
#define NSPLIT    7
#define NTH       512
#define NWARP     (NTH / 32)
#define SR_PAD    96
#define SR_TOT    (SR_PAD + RIR_LEN + 96)   /* 8192 floats = 32 KB */
#define PI_F      3.14159265358979323846f
#define INV_PI_F  0.3183098861837907f
#define FS_OVER_C 46.64723032069971f   /* 16000 / 343 */

// ---------------------------------------------------------------------------
// Per-(room, image-range) partial RIR in guard-padded shared memory,
// RED.ADD into out. out RIR region pre-zeroed by a memset node.
// ---------------------------------------------------------------------------
__global__ void __launch_bounds__(NTH, 3)
rir_partial_kernel(const float* __restrict__ in, float* __restrict__ out, int B)
{
    __shared__ float  srir[SR_TOT];        // 32768 B, guards at both ends
    __shared__ float4 stage[NWARP][32];    // {delay, a2, a2*hc, a2*hs} : 8 KB
    __shared__ float  prm[10];
    __shared__ float  roomS[3], micS[3], srcS[3];
    __shared__ float  trp[11];             // tr^k
    __shared__ int    pfx[22];             // image-index prefix per gx shell

    const int b    = blockIdx.x / NSPLIT;  // room
    const int sub  = blockIdx.x % NSPLIT;  // image-range split
    const int tid  = threadIdx.x;
    const int lane = tid & 31;
    const int warp = tid >> 5;

    if (tid < 10) prm[tid] = in[b * 10 + tid];
    if (tid < 22) {
        int n = tid, v;
        if (n <= 10) v = (n - 1) * n * (2 * n - 1) / 3 + (n - 1) * n + n;
        else { int m = 21 - n; v = NIMG - ((m - 1) * m * (2 * m - 1) / 3 + (m - 1) * m + m); }
        pfx[tid] = v;
    }
    {
        float4* s4 = (float4*)srir;
        for (int i = tid; i < SR_TOT / 4; i += NTH)
            s4[i] = make_float4(0.f, 0.f, 0.f, 0.f);
    }
    __syncthreads();

    if (tid < 3) {
        float r = prm[tid];
        roomS[tid] = r;
        micS[tid]  = prm[3 + tid] * r;
        srcS[tid]  = prm[6 + tid] * r;
    }
    if (tid < 11) trp[tid] = powf(sqrtf(1.0f - prm[9]), (float)tid);

    // Per-lane Hann basis with (-1)^t folded in:
    // tap t in {lane, lane+32, lane+64}; sgn = (-1)^t depends only on lane.
    const float sgn  = (lane & 1) ? -1.0f : 1.0f;
    const float tmf0 = (float)(lane - 40);
    const float tmf1 = (float)(lane - 8);
    const float tmf2 = (float)(lane + 24);
    float c0s, ns0s, c1s, ns1s, c2s, ns2s, sv, cv;
    sincosf(PI_F * (1.0f / 40.0f) * tmf0, &sv, &cv); c0s = cv * sgn; ns0s = -sv * sgn;
    sincosf(PI_F * (1.0f / 40.0f) * tmf1, &sv, &cv); c1s = cv * sgn; ns1s = -sv * sgn;
    sincosf(PI_F * (1.0f / 40.0f) * tmf2, &sv, &cv); c2s = cv * sgn; ns2s = -sv * sgn;
    const float half_s = 0.5f * sgn;
    __syncthreads();

    // image sub-range for this CTA, chunked evenly over warps
    const int is    = (NIMG * sub)       / NSPLIT;
    const int ie    = (NIMG * (sub + 1)) / NSPLIT;
    const int chunk = (ie - is + NWARP - 1) / NWARP;
    const int ws    = min(is + warp * chunk, ie);
    const int we    = min(ws + chunk, ie);

    for (int i0 = ws; i0 < we; i0 += 32) {
        const int i = i0 + lane;

        // ---------- lane-parallel per-image scalar phase ----------
        {
            float4 st = make_float4(1e9f, 0.f, 0.f, 0.f);  // delay sentinel -> skip
            if (i < we) {
                // decode image index -> (gx, gy, gz), |gx|+|gy|+|gz| <= 10
                int lo = 0, hi = 21;
#pragma unroll
                for (int it = 0; it < 5; it++) {
                    int mid = (lo + hi) >> 1;
                    if (i >= pfx[mid]) lo = mid; else hi = mid;
                }
                const int gx = lo - 10;
                const int ax = gx < 0 ? -gx : gx;
                const int R  = 10 - ax;
                const int j  = i - pfx[lo];
                const int M  = 2 * R * R + 2 * R + 1;
                const int rp1 = R + 1;
                int k;
                if (j < rp1 * rp1) k = (int)sqrtf((float)j + 0.5f);
                else               k = 2 * R - (int)sqrtf((float)(M - 1 - j) + 0.5f);
                const int Pk = (k <= R) ? k * k : M - (2 * R + 1 - k) * (2 * R + 1 - k);
                const int gy = k - R;
                const int ay = gy < 0 ? -gy : gy;
                const int gz = (j - Pk) - (R - ay);
                const int az = gz < 0 ? -gz : gz;

                const float att = trp[ax + ay + az];
                const int g3[3] = {gx, gy, gz};
                float d2 = 0.0f;
#pragma unroll
                for (int d = 0; d < 3; d++) {
                    const int   g  = g3[d];
                    const float gf = (float)g;
                    const float ip = (g & 1) ? roomS[d] * (gf + 1.0f) - srcS[d]
                                             : roomS[d] * gf + srcS[d];
                    const float df = ip - micS[d];
                    d2 += df * df;
                }
                const float dist    = sqrtf(d2);
                const float amp     = __fdividef(att, dist);
                const float delay   = dist * FS_OVER_C;
                const float delay_i = ceilf(delay);
                const float fr      = fmaxf(delay_i - delay, 1e-9f);

                // ACCURATE sinf required: __sinf's ~4e-7 abs error explodes
                // when divided by pi*fr with fr ~ 1e-9 (R10 failure)
                const float s  = sinf(PI_F * fr);
                float sA, cA;
                __sincosf(PI_F * (1.0f / 40.0f) * fr, &sA, &cA);

                const float a2 = amp * s * INV_PI_F;
                st = make_float4(delay, a2, a2 * 0.5f * cA, a2 * 0.5f * sA);
            }
            stage[warp][lane] = st;
        }
        __syncwarp();

        // ---------- warp-cooperative tap scatter (branchless, guarded smem) --
        const int nv = min(32, we - i0);
        for (int jj = 0; jj < nv; jj++) {
            const float4 v  = stage[warp][jj];
            const float  di = ceilf(v.x);
            const int  base = (int)di - 40;
            if (base >= RIR_LEN) continue;          // fully clipped image
            const float fr = fmaxf(di - v.x, 1e-9f);
            const float q  = v.y * half_s;
            const float pc = v.z;
            const float ps = v.w;
            const int   ib = SR_PAD + base + lane;

            {   // t = lane
                const float x = fr + tmf0;
                const float w = fmaf(pc, c0s, fmaf(ps, ns0s, q));
                atomicAdd(&srir[ib], __fdividef(w, x));
            }
            {   // t = lane + 32
                const float x = fr + tmf1;
                const float w = fmaf(pc, c1s, fmaf(ps, ns1s, q));
                atomicAdd(&srir[ib + 32], __fdividef(w, x));
            }
            if (lane < 16) {   // t = lane + 64 (t=80 tap identically zero)
                const float x = fr + tmf2;
                const float w = fmaf(pc, c2s, fmaf(ps, ns2s, q));
                atomicAdd(&srir[ib + 64], __fdividef(w, x));
            }
        }
    }
    __syncthreads();

    // RED.ADD this CTA's partial RIR into the output row (guards dropped)
    {
        float* orow = out + (size_t)b * RIR_LEN;
        for (int i = tid; i < RIR_LEN; i += NTH)
            atomicAdd(&orow[i], srir[SR_PAD + i]);
    }

    // TOA (single writer per room, plain store)
    if (sub == 0 && tid == 0) {
        const float d0 = micS[0] - srcS[0];
        const float d1 = micS[1] - srcS[1];
        const float d2 = micS[2] - srcS[2];
        out[(size_t)B * RIR_LEN + b] =
            40.0f + FS_OVER_C * sqrtf(d0 * d0 + d1 * d1 + d2 * d2);
    }
}

extern "C" void kernel_launch(void* const* d_in, const int* in_sizes, int n_in,
                              void* d_out, int out_size)
{
    const float* in  = (const float*)d_in[0];
    float*       out = (float*)d_out;
    const int B = in_sizes[0] / 10;          // 256 rooms x 10 params
    // zero RIR region via capturable memset node (TOA region overwritten later)
    cudaMemsetAsync(out, 0, (size_t)B * RIR_LEN * sizeof(float));
    rir_partial_kernel<<<B * NSPLIT, NTH>>>(in, out, B);
}

// round 17
// speedup vs baseline: 1.4544x; 1.4544x over previous
#include <cuda_runtime.h>
#include <cuda_bf16.h>

#define RIR_LEN   8000
#define NIMG      1561
#define NTH       512
#define NWARP     (NTH / 32)
#define PI_F      3.14159265358979323846f
#define INV_PI_F  0.3183098861837907f
#define FS_OVER_C 46.64723032069971f   /* 16000 / 343 */

// ---------------------------------------------------------------------------
// Per-(room, image-range) partial RIR in shared memory, RED.ADD into out.
// out RIR region pre-zeroed by a memset node.
// Uneven room splits (7 or 6) so grid = 1776 = 3 * (148 SM * 4 CTA) exactly.
// ---------------------------------------------------------------------------
__global__ void __launch_bounds__(NTH, 4)
rir_partial_kernel(const float* __restrict__ in, float* __restrict__ out,
                   int B, int n7, int thr)
{
    __shared__ float  srir[RIR_LEN];     // 32000 B
    __shared__ float4 htab4[32];         // {c0*sg, -s0*sg, c1*sg, -s1*sg} per lane
    __shared__ float2 htab2[32];         // {c2*sg, -s2*sg} per lane
    __shared__ float  prm[10];
    __shared__ float  roomS[3], micS[3], srcS[3];
    __shared__ float  trp[11];           // tr^k
    __shared__ int    pfx[22];           // image-index prefix per gx shell

    // uneven split mapping: rooms [0,n7) have 7 subs, rooms [n7,B) have 6
    int b, sub, ns;
    if ((int)blockIdx.x < thr) { b = blockIdx.x / 7;        sub = blockIdx.x % 7; ns = 7; }
    else { int r = blockIdx.x - thr; b = n7 + r / 6;        sub = r % 6;          ns = 6; }

    const int tid  = threadIdx.x;
    const int lane = tid & 31;
    const int warp = tid >> 5;

    if (tid < 10) prm[tid] = in[b * 10 + tid];
    if (tid < 22) {
        int n = tid, v;
        if (n <= 10) v = (n - 1) * n * (2 * n - 1) / 3 + (n - 1) * n + n;
        else { int m = 21 - n; v = NIMG - ((m - 1) * m * (2 * m - 1) / 3 + (m - 1) * m + m); }
        pfx[tid] = v;
    }
    if (tid < 32) {
        // Hann basis with sinc parity sign (-1)^t folded in; t = tid + 32r
        const float sg = (tid & 1) ? -1.0f : 1.0f;
        float s, c;
        sincosf(PI_F * (1.0f / 40.0f) * (float)(tid - 40), &s, &c);
        float4 h4; h4.x = c * sg; h4.y = -s * sg;
        sincosf(PI_F * (1.0f / 40.0f) * (float)(tid - 8), &s, &c);
        h4.z = c * sg; h4.w = -s * sg;
        htab4[tid] = h4;
        sincosf(PI_F * (1.0f / 40.0f) * (float)(tid + 24), &s, &c);
        htab2[tid] = make_float2(c * sg, -s * sg);
    }
    {
        float4* s4 = (float4*)srir;
        for (int i = tid; i < RIR_LEN / 4; i += NTH)
            s4[i] = make_float4(0.f, 0.f, 0.f, 0.f);
    }
    __syncthreads();

    if (tid < 3) {
        float r = prm[tid];
        roomS[tid] = r;
        micS[tid]  = prm[3 + tid] * r;
        srcS[tid]  = prm[6 + tid] * r;
    }
    if (tid < 11) trp[tid] = powf(sqrtf(1.0f - prm[9]), (float)tid);
    const float sgn  = (lane & 1) ? -1.0f : 1.0f;
    const float tmf0 = (float)(lane - 40);
    const float tmf1 = (float)(lane - 8);
    const float tmf2 = (float)(lane + 24);
    __syncthreads();

    // image sub-range for this CTA, chunked evenly over warps
    const int is    = (NIMG * sub)       / ns;
    const int ie    = (NIMG * (sub + 1)) / ns;
    const int chunk = (ie - is + NWARP - 1) / NWARP;
    const int ws    = min(is + warp * chunk, ie);
    const int we    = min(ws + chunk, ie);

    for (int i0 = ws; i0 < we; i0 += 32) {
        const int i = i0 + lane;

        // ---------- lane-parallel per-image scalar phase ----------
        float frL = 0.0f, q0L = 0.0f, pcL = 0.0f, psL = 0.0f;
        int   baseL = RIR_LEN;
        if (i < we) {
            // decode image index -> (gx, gy, gz), |gx|+|gy|+|gz| <= 10
            int lo = 0, hi = 21;
#pragma unroll
            for (int it = 0; it < 5; it++) {
                int mid = (lo + hi) >> 1;
                if (i >= pfx[mid]) lo = mid; else hi = mid;
            }
            const int gx = lo - 10;
            const int ax = gx < 0 ? -gx : gx;
            const int R  = 10 - ax;
            const int j  = i - pfx[lo];
            const int M  = 2 * R * R + 2 * R + 1;
            const int rp1 = R + 1;
            int k;
            if (j < rp1 * rp1) k = (int)sqrtf((float)j + 0.5f);
            else               k = 2 * R - (int)sqrtf((float)(M - 1 - j) + 0.5f);
            const int Pk = (k <= R) ? k * k : M - (2 * R + 1 - k) * (2 * R + 1 - k);
            const int gy = k - R;
            const int ay = gy < 0 ? -gy : gy;
            const int gz = (j - Pk) - (R - ay);
            const int az = gz < 0 ? -gz : gz;

            const float att = trp[ax + ay + az];
            const int g3[3] = {gx, gy, gz};
            float d2 = 0.0f;
#pragma unroll
            for (int d = 0; d < 3; d++) {
                const int   g  = g3[d];
                const float gf = (float)g;
                const float ip = (g & 1) ? roomS[d] * (gf + 1.0f) - srcS[d]
                                         : roomS[d] * gf + srcS[d];
                const float df = ip - micS[d];
                d2 += df * df;
            }
            const float dist    = sqrtf(d2);
            const float amp     = __fdividef(att, dist);
            const float delay   = dist * FS_OVER_C;
            const float delay_i = ceilf(delay);
            // clamp frac away from 0: sin(pi*fr)/(pi*x) reproduces sinc(0)=1
            // to ~1e-9 abs, so no x==0 special case needed
            const float fr = fmaxf(delay_i - delay, 1e-9f);

            // ACCURATE sinf required: __sinf's ~4e-7 abs error explodes when
            // divided by pi*fr with fr ~ 1e-9 (R10 failure)
            const float s = sinf(PI_F * fr);
            float sA, cA;
            __sincosf(PI_F * (1.0f / 40.0f) * fr, &sA, &cA);

            const float a2 = amp * s * INV_PI_F;
            frL   = fr;
            q0L   = 0.5f * a2;          // tap value = sg*(q0 + pc*c - ps*s)/x
            pcL   = q0L * cA;
            psL   = q0L * sA;
            baseL = (int)delay_i - 40;
        }

        // ---------- warp-cooperative tap scatter (conflict-free) ----------
        const int nv = min(32, we - i0);
        for (int jj = 0; jj < nv; jj++) {
            const int base = __shfl_sync(0xffffffffu, baseL, jj);
            if (base >= RIR_LEN) continue;         // fully clipped image
            const float fr = __shfl_sync(0xffffffffu, frL, jj);
            const float q0 = __shfl_sync(0xffffffffu, q0L, jj);
            const float pc = __shfl_sync(0xffffffffu, pcL, jj);
            const float ps = __shfl_sync(0xffffffffu, psL, jj);

            const float  qL = q0 * sgn;            // fold (-1)^t (lane parity)
            const float4 h4 = htab4[lane];
            const float2 h2 = htab2[lane];
            const float x0 = fr + tmf0;
            const float x1 = fr + tmf1;
            const float x2 = fr + tmf2;
            const float w0 = fmaf(pc, h4.x, fmaf(ps, h4.y, qL));
            const float w1 = fmaf(pc, h4.z, fmaf(ps, h4.w, qL));
            const float w2 = fmaf(pc, h2.x, fmaf(ps, h2.y, qL));
            const int   ib = base + lane;

            if (base >= 0 && base < RIR_LEN - 80) {
                // interior fast path: no per-tap bounds checks
                atomicAdd(&srir[ib],      __fdividef(w0, x0));
                atomicAdd(&srir[ib + 32], __fdividef(w1, x1));
                if (lane < 16)   // t=80 tap identically zero
                    atomicAdd(&srir[ib + 64], __fdividef(w2, x2));
            } else {
                if ((unsigned)ib < RIR_LEN)
                    atomicAdd(&srir[ib], __fdividef(w0, x0));
                if ((unsigned)(ib + 32) < RIR_LEN)
                    atomicAdd(&srir[ib + 32], __fdividef(w1, x1));
                if (lane < 16 && (unsigned)(ib + 64) < RIR_LEN)
                    atomicAdd(&srir[ib + 64], __fdividef(w2, x2));
            }
        }
    }
    __syncthreads();

    // RED.ADD this CTA's partial RIR into the output row (coalesced, no-return)
    {
        float* orow = out + (size_t)b * RIR_LEN;
        for (int i = tid; i < RIR_LEN; i += NTH)
            atomicAdd(&orow[i], srir[i]);
    }

    // TOA (single writer per room, plain store)
    if (sub == 0 && tid == 0) {
        const float d0 = micS[0] - srcS[0];
        const float d1 = micS[1] - srcS[1];
        const float d2 = micS[2] - srcS[2];
        out[(size_t)B * RIR_LEN + b] =
            40.0f + FS_OVER_C * sqrtf(d0 * d0 + d1 * d1 + d2 * d2);
    }
}

extern "C" void kernel_launch(void* const* d_in, const int* in_sizes, int n_in,
                              void* d_out, int out_size)
{
    const float* in  = (const float*)d_in[0];
    float*       out = (float*)d_out;
    const int B = in_sizes[0] / 10;          // 256 rooms x 10 params
    // uneven splits: n7 rooms get 7 CTAs, rest get 6 -> grid multiple of 592
    const int n7   = (B == 256) ? 240 : B;   // 240*7 + 16*6 = 1776 = 3*592
    const int thr  = n7 * 7;
    const int grid = thr + (B - n7) * 6;
    cudaMemsetAsync(out, 0, (size_t)B * RIR_LEN * sizeof(float));
    rir_partial_kernel<<<grid, NTH>>>(in, out, B, n7, thr);
}